// round 3
// baseline (speedup 1.0000x reference)
#include <cuda_runtime.h>
#include <cuda_fp16.h>
#include <math.h>

#define DIMV 2048
#define NTR  4096
#define MDEVR 8192
#define TST  500
#define ETA  0.1f
#define NTHREADS 256
#define NWARPS 8
#define MAXCTA 320

// Persistent device state (static allocation — no cudaMalloc anywhere)
__device__ float    g_theta[DIMV];
__device__ float    g_devpart[MAXCTA];
__device__ float    g_gradpart[MAXCTA * DIMV];
__device__ unsigned g_arrive;
// fp16 copies of the big matrices (halves L2 footprint + bytes/step)
__device__ __half   g_xn_h[(size_t)NTR * DIMV];     // 16.8 MB
__device__ __half   g_dxn_h[(size_t)MDEVR * DIMV];  // 33.6 MB

// ---------------------------------------------------------------------------
__global__ void ak_init(const float* __restrict__ theta0,
                        float* __restrict__ out, int out_size) {
    int i = blockIdx.x * blockDim.x + threadIdx.x;
    if (i == 0) g_arrive = 0u;
    if (i < DIMV) g_theta[i] = theta0[i];
    for (int j = TST + 1 + i; j < out_size; j += gridDim.x * blockDim.x)
        out[j] = 0.0f;
}

// fp32 -> fp16 conversion of xn and dev_xn (vectorized, grid-stride)
__global__ void ak_convert(const float* __restrict__ xn,
                           const float* __restrict__ dxn) {
    const size_t n4  = (size_t)NTR * DIMV / 4;
    const size_t m4  = (size_t)MDEVR * DIMV / 4;
    const float4* s0 = (const float4*)xn;
    const float4* s1 = (const float4*)dxn;
    __half2* d0 = (__half2*)g_xn_h;
    __half2* d1 = (__half2*)g_dxn_h;
    size_t stride = (size_t)gridDim.x * blockDim.x;
    for (size_t i = blockIdx.x * (size_t)blockDim.x + threadIdx.x; i < n4; i += stride) {
        float4 v = s0[i];
        d0[2*i+0] = __floats2half2_rn(v.x, v.y);
        d0[2*i+1] = __floats2half2_rn(v.z, v.w);
    }
    for (size_t i = blockIdx.x * (size_t)blockDim.x + threadIdx.x; i < m4; i += stride) {
        float4 v = s1[i];
        d1[2*i+0] = __floats2half2_rn(v.x, v.y);
        d1[2*i+1] = __floats2half2_rn(v.z, v.w);
    }
}

// Grid-wide barrier (atomic counter + generation; gpu-scope fences)
__device__ __forceinline__ void grid_barrier(unsigned nb) {
    __syncthreads();
    if (threadIdx.x == 0) {
        __threadfence();
        unsigned old = atomicAdd(&g_arrive, 1u);
        unsigned target = (old / nb + 1u) * nb;
        while (*((volatile unsigned*)&g_arrive) < target) { }
        __threadfence();
    }
    __syncthreads();
}

__device__ __forceinline__ float warp_sum(float v) {
#pragma unroll
    for (int o = 16; o; o >>= 1) v += __shfl_xor_sync(0xffffffffu, v, o);
    return v;
}

__device__ __forceinline__ float dev_loss_elem(float z, float y) {
    return fmaxf(z, 0.0f) - y * z + log1pf(expf(-fabsf(z)));
}

// half2 dot chunk: acc2[p] += x[p] * th2[p], p = 0..3 (8 halves from uint4)
__device__ __forceinline__ void dot8h(__half2* acc2, const uint4& u, const __half2* th2j) {
    const __half2* h = (const __half2*)&u;
    acc2[0] = __hfma2(h[0], th2j[0], acc2[0]);
    acc2[1] = __hfma2(h[1], th2j[1], acc2[1]);
    acc2[2] = __hfma2(h[2], th2j[2], acc2[2]);
    acc2[3] = __hfma2(h[3], th2j[3], acc2[3]);
}

__device__ __forceinline__ void grad8h(__half2* gj, const uint4& u, __half2 ch2) {
    const __half2* h = (const __half2*)&u;
    gj[0] = __hfma2(ch2, h[0], gj[0]);
    gj[1] = __hfma2(ch2, h[1], gj[1]);
    gj[2] = __hfma2(ch2, h[2], gj[2]);
    gj[3] = __hfma2(ch2, h[3], gj[3]);
}

__device__ __forceinline__ float acc4_to_float(const __half2* a) {
    float2 f0 = __half22float2(a[0]);
    float2 f1 = __half22float2(a[1]);
    float2 f2 = __half22float2(a[2]);
    float2 f3 = __half22float2(a[3]);
    return (f0.x + f0.y) + (f1.x + f1.y) + (f2.x + f2.y) + (f3.x + f3.y);
}

// ---------------------------------------------------------------------------
__global__ void __launch_bounds__(NTHREADS, 2)
ak_train(const float* __restrict__ yn,  const float* __restrict__ dyn,
         const float* __restrict__ alphas,
         float* __restrict__ out, int out_size) {
    extern __shared__ char smc[];
    __half* s_grad = (__half*)smc;                       // NWARPS * DIMV halves (32KB)
    float*  s_dev  = (float*)(smc + NWARPS * DIMV * 2);  // NWARPS floats

    const int tid  = threadIdx.x;
    const int lane = tid & 31;
    const int w    = tid >> 5;
    const int cta  = blockIdx.x;
    const int ncta = gridDim.x;
    const int gw   = cta * NWARPS + w;
    const int nw   = ncta * NWARPS;

    __half2 th2[32];   // th2[j*4+p] = theta[(j*32+lane)*8 + 2p .. +2p+1]

    for (int t = 0; t < TST; ++t) {
        // ---- theta -> half2 registers
        {
            const float4* t4 = (const float4*)g_theta;
#pragma unroll
            for (int j = 0; j < 8; j++) {
                float4 v0 = t4[(j*32+lane)*2 + 0];
                float4 v1 = t4[(j*32+lane)*2 + 1];
                th2[j*4+0] = __floats2half2_rn(v0.x, v0.y);
                th2[j*4+1] = __floats2half2_rn(v0.z, v0.w);
                th2[j*4+2] = __floats2half2_rn(v1.x, v1.y);
                th2[j*4+3] = __floats2half2_rn(v1.z, v1.w);
            }
        }

        // ---- train rows: dual-row dot + fused gradient accumulation
        __half2 hacc[32];
        const __half2 hz = __float2half2_rn(0.0f);
#pragma unroll
        for (int j = 0; j < 32; j++) hacc[j] = hz;

        int n0 = gw;
        for (; n0 + nw < NTR; n0 += 2*nw) {
            int n1 = n0 + nw;
            const uint4* x0 = (const uint4*)(g_xn_h + (size_t)n0 * DIMV);
            const uint4* x1 = (const uint4*)(g_xn_h + (size_t)n1 * DIMV);
            __half2 a0[4] = {hz,hz,hz,hz}, a1[4] = {hz,hz,hz,hz};
#pragma unroll
            for (int j = 0; j < 8; j++) {
                uint4 ua = x0[j*32+lane];
                uint4 ub = x1[j*32+lane];
                dot8h(a0, ua, th2 + j*4);
                dot8h(a1, ub, th2 + j*4);
            }
            float z0 = warp_sum(acc4_to_float(a0));
            float z1 = warp_sum(acc4_to_float(a1));
            float s0 = 1.0f / (1.0f + expf(-z0));
            float s1 = 1.0f / (1.0f + expf(-z1));
            float c0 = alphas[(size_t)t * NTR + n0] * (s0 - yn[n0]);
            float c1 = alphas[(size_t)t * NTR + n1] * (s1 - yn[n1]);
            __half2 ch0 = __float2half2_rn(c0);
            __half2 ch1 = __float2half2_rn(c1);
#pragma unroll
            for (int j = 0; j < 8; j++) {
                uint4 ua = x0[j*32+lane];   // L1 hits
                uint4 ub = x1[j*32+lane];
                grad8h(hacc + j*4, ua, ch0);
                grad8h(hacc + j*4, ub, ch1);
            }
        }
        if (n0 < NTR) {  // tail single row
            const uint4* x0 = (const uint4*)(g_xn_h + (size_t)n0 * DIMV);
            __half2 a0[4] = {hz,hz,hz,hz};
#pragma unroll
            for (int j = 0; j < 8; j++) { uint4 ua = x0[j*32+lane]; dot8h(a0, ua, th2 + j*4); }
            float z0 = warp_sum(acc4_to_float(a0));
            float s0 = 1.0f / (1.0f + expf(-z0));
            float c0 = alphas[(size_t)t * NTR + n0] * (s0 - yn[n0]);
            __half2 ch0 = __float2half2_rn(c0);
#pragma unroll
            for (int j = 0; j < 8; j++) { uint4 ua = x0[j*32+lane]; grad8h(hacc + j*4, ua, ch0); }
        }
        // dump per-warp grad partial as half2 (d = (j*32+lane)*8 + q)
        {
            uint4* gp4 = (uint4*)(s_grad + (size_t)w * DIMV);
#pragma unroll
            for (int j = 0; j < 8; j++) {
                uint4 u;
                ((__half2*)&u)[0] = hacc[j*4+0];
                ((__half2*)&u)[1] = hacc[j*4+1];
                ((__half2*)&u)[2] = hacc[j*4+2];
                ((__half2*)&u)[3] = hacc[j*4+3];
                gp4[j*32+lane] = u;
            }
        }

        // ---- dev loss with current theta (= full_losses[t]), dual-row
        float dsum = 0.0f;
        int m0 = gw;
        for (; m0 + nw < MDEVR; m0 += 2*nw) {
            int m1 = m0 + nw;
            const uint4* x0 = (const uint4*)(g_dxn_h + (size_t)m0 * DIMV);
            const uint4* x1 = (const uint4*)(g_dxn_h + (size_t)m1 * DIMV);
            __half2 a0[4] = {hz,hz,hz,hz}, a1[4] = {hz,hz,hz,hz};
#pragma unroll
            for (int j = 0; j < 8; j++) {
                uint4 ua = x0[j*32+lane];
                uint4 ub = x1[j*32+lane];
                dot8h(a0, ua, th2 + j*4);
                dot8h(a1, ub, th2 + j*4);
            }
            float z0 = warp_sum(acc4_to_float(a0));
            float z1 = warp_sum(acc4_to_float(a1));
            dsum += dev_loss_elem(z0, dyn[m0]) + dev_loss_elem(z1, dyn[m1]);
        }
        if (m0 < MDEVR) {
            const uint4* x0 = (const uint4*)(g_dxn_h + (size_t)m0 * DIMV);
            __half2 a0[4] = {hz,hz,hz,hz};
#pragma unroll
            for (int j = 0; j < 8; j++) { uint4 ua = x0[j*32+lane]; dot8h(a0, ua, th2 + j*4); }
            dsum += dev_loss_elem(warp_sum(acc4_to_float(a0)), dyn[m0]);
        }
        if (lane == 0) s_dev[w] = dsum;
        __syncthreads();
        if (tid == 0) {
            float s = 0.0f;
#pragma unroll
            for (int i = 0; i < NWARPS; i++) s += s_dev[i];
            g_devpart[cta] = s;
        }
        // CTA-level grad partial (fixed warp order -> deterministic), half2 lanes
        {
            const __half2* sg2 = (const __half2*)s_grad;
            float2* gp2 = (float2*)(g_gradpart + (size_t)cta * DIMV);
#pragma unroll
            for (int i = 0; i < (DIMV/2) / NTHREADS; i++) {
                int idx = tid + i * NTHREADS;
                float2 s = make_float2(0.0f, 0.0f);
#pragma unroll
                for (int ww = 0; ww < NWARPS; ww++) {
                    float2 f = __half22float2(sg2[ww * (DIMV/2) + idx]);
                    s.x += f.x; s.y += f.y;
                }
                gp2[idx] = s;
            }
        }

        grid_barrier((unsigned)ncta);

        // ---- phase B: reduce partials, update theta, record loss
        {
            int gid = cta * NTHREADS + tid;
            int d = gid >> 4, sub = gid & 15;
            if (d < DIMV) {
                float s = 0.0f;
                for (int r = sub; r < ncta; r += 16)
                    s += g_gradpart[r * DIMV + d];
#pragma unroll
                for (int o = 8; o; o >>= 1)
                    s += __shfl_xor_sync(0xffffffffu, s, o);
                if (sub == 0) g_theta[d] = g_theta[d] - ETA * s;
            }
            if (cta == ncta - 1 && tid == 0) {
                float s = 0.0f;
                for (int c = 0; c < ncta; c++) s += g_devpart[c];
                if (1 + t < out_size) out[1 + t] = s * (1.0f / MDEVR);
            }
        }
        grid_barrier((unsigned)ncta);
    }

    // ---- final dev eval at theta_T; finalize scalar loss
    {
        const float4* t4 = (const float4*)g_theta;
#pragma unroll
        for (int j = 0; j < 8; j++) {
            float4 v0 = t4[(j*32+lane)*2 + 0];
            float4 v1 = t4[(j*32+lane)*2 + 1];
            th2[j*4+0] = __floats2half2_rn(v0.x, v0.y);
            th2[j*4+1] = __floats2half2_rn(v0.z, v0.w);
            th2[j*4+2] = __floats2half2_rn(v1.x, v1.y);
            th2[j*4+3] = __floats2half2_rn(v1.z, v1.w);
        }
        const __half2 hz = __float2half2_rn(0.0f);
        float dsum = 0.0f;
        int m0 = gw;
        for (; m0 + nw < MDEVR; m0 += 2*nw) {
            int m1 = m0 + nw;
            const uint4* x0 = (const uint4*)(g_dxn_h + (size_t)m0 * DIMV);
            const uint4* x1 = (const uint4*)(g_dxn_h + (size_t)m1 * DIMV);
            __half2 a0[4] = {hz,hz,hz,hz}, a1[4] = {hz,hz,hz,hz};
#pragma unroll
            for (int j = 0; j < 8; j++) {
                uint4 ua = x0[j*32+lane];
                uint4 ub = x1[j*32+lane];
                dot8h(a0, ua, th2 + j*4);
                dot8h(a1, ub, th2 + j*4);
            }
            dsum += dev_loss_elem(warp_sum(acc4_to_float(a0)), dyn[m0])
                  + dev_loss_elem(warp_sum(acc4_to_float(a1)), dyn[m1]);
        }
        if (m0 < MDEVR) {
            const uint4* x0 = (const uint4*)(g_dxn_h + (size_t)m0 * DIMV);
            __half2 a0[4] = {hz,hz,hz,hz};
#pragma unroll
            for (int j = 0; j < 8; j++) { uint4 ua = x0[j*32+lane]; dot8h(a0, ua, th2 + j*4); }
            dsum += dev_loss_elem(warp_sum(acc4_to_float(a0)), dyn[m0]);
        }
        if (lane == 0) s_dev[w] = dsum;
        __syncthreads();
        if (tid == 0) {
            float s = 0.0f;
#pragma unroll
            for (int i = 0; i < NWARPS; i++) s += s_dev[i];
            g_devpart[cta] = s;
        }
        grid_barrier((unsigned)ncta);
        if (cta == 0 && tid == 0) {
            float s = 0.0f;
            for (int c = 0; c < ncta; c++) s += g_devpart[c];
            float LT = s * (1.0f / MDEVR);
            float isum = 0.0f;
            for (int t = 1; t < TST; t++)
                isum += (1 + t < out_size) ? out[1 + t] : 0.0f;
            isum += LT;
            if (out_size > 0) out[0] = isum / (float)TST;
        }
    }
}

// ---------------------------------------------------------------------------
extern "C" void kernel_launch(void* const* d_in, const int* in_sizes, int n_in,
                              void* d_out, int out_size) {
    const float *theta = nullptr, *alphas = nullptr, *xn = nullptr,
                *yn = nullptr, *dxn = nullptr, *dyn = nullptr;
    for (int i = 0; i < n_in; i++) {
        switch (in_sizes[i]) {
            case DIMV:         theta  = (const float*)d_in[i]; break;
            case TST * NTR:    alphas = (const float*)d_in[i]; break;
            case NTR * DIMV:   xn     = (const float*)d_in[i]; break;
            case NTR:          yn     = (const float*)d_in[i]; break;
            case MDEVR * DIMV: dxn    = (const float*)d_in[i]; break;
            case MDEVR:        dyn    = (const float*)d_in[i]; break;
            default: break;
        }
    }
    float* out = (float*)d_out;

    int dev = 0;
    cudaGetDevice(&dev);
    int nsm = 148;
    cudaDeviceGetAttribute(&nsm, cudaDevAttrMultiProcessorCount, dev);
    int ncta = 2 * nsm;
    if (ncta > MAXCTA) ncta = MAXCTA;
    if (ncta < 1) ncta = 1;

    size_t smem = (size_t)NWARPS * DIMV * 2 + NWARPS * sizeof(float); // ~32KB
    cudaFuncSetAttribute(ak_train, cudaFuncAttributeMaxDynamicSharedMemorySize,
                         (int)smem);

    ak_init<<<(DIMV + 255) / 256, 256>>>(theta, out, out_size);
    ak_convert<<<4 * nsm, 256>>>(xn, dxn);
    ak_train<<<ncta, NTHREADS, smem>>>(yn, dyn, alphas, out, out_size);
}

// round 4
// speedup vs baseline: 1.3510x; 1.3510x over previous
#include <cuda_runtime.h>
#include <cuda_fp16.h>
#include <math.h>

#define DIMV 2048
#define NTR  4096
#define MDEVR 8192
#define TST  500
#define ETA  0.1f
#define NTHREADS 256
#define NWARPS 8

#define S_GRAD_F   1.7179869184e10f   /* 2^34 */
#define INV_SGRAD  5.8207660913e-11f  /* 2^-34 */
#define S_DEV_F    4.294967296e9f     /* 2^32 */
#define INV_SDEV   2.3283064365e-10f  /* 2^-32 */

// Persistent device state (static allocation — no cudaMalloc anywhere)
__device__ unsigned long long g_gradacc[DIMV];  // fixed-point running totals
__device__ unsigned long long g_devacc;
__device__ unsigned           g_arrive;
// fp16 copies of the big matrices
__device__ __half g_xn_h[(size_t)NTR * DIMV];     // 16.8 MB
__device__ __half g_dxn_h[(size_t)MDEVR * DIMV];  // 33.6 MB

// ---------------------------------------------------------------------------
__global__ void ak_init(float* __restrict__ out, int out_size) {
    int i = blockIdx.x * blockDim.x + threadIdx.x;
    if (i == 0) { g_arrive = 0u; g_devacc = 0ull; }
    if (i < DIMV) g_gradacc[i] = 0ull;
    for (int j = TST + 1 + i; j < out_size; j += gridDim.x * blockDim.x)
        out[j] = 0.0f;
}

__global__ void ak_convert(const float* __restrict__ xn,
                           const float* __restrict__ dxn) {
    const size_t n4  = (size_t)NTR * DIMV / 4;
    const size_t m4  = (size_t)MDEVR * DIMV / 4;
    const float4* s0 = (const float4*)xn;
    const float4* s1 = (const float4*)dxn;
    __half2* d0 = (__half2*)g_xn_h;
    __half2* d1 = (__half2*)g_dxn_h;
    size_t stride = (size_t)gridDim.x * blockDim.x;
    for (size_t i = blockIdx.x * (size_t)blockDim.x + threadIdx.x; i < n4; i += stride) {
        float4 v = s0[i];
        d0[2*i+0] = __floats2half2_rn(v.x, v.y);
        d0[2*i+1] = __floats2half2_rn(v.z, v.w);
    }
    for (size_t i = blockIdx.x * (size_t)blockDim.x + threadIdx.x; i < m4; i += stride) {
        float4 v = s1[i];
        d1[2*i+0] = __floats2half2_rn(v.x, v.y);
        d1[2*i+1] = __floats2half2_rn(v.z, v.w);
    }
}

// Grid-wide barrier (atomic counter + generation; gpu-scope fences)
__device__ __forceinline__ void grid_barrier(unsigned nb) {
    __syncthreads();
    if (threadIdx.x == 0) {
        __threadfence();
        unsigned old = atomicAdd(&g_arrive, 1u);
        unsigned target = (old / nb + 1u) * nb;
        while (*((volatile unsigned*)&g_arrive) < target) { }
        __threadfence();
    }
    __syncthreads();
}

__device__ __forceinline__ float warp_sum(float v) {
#pragma unroll
    for (int o = 16; o; o >>= 1) v += __shfl_xor_sync(0xffffffffu, v, o);
    return v;
}

__device__ __forceinline__ float dev_loss_elem(float z, float y) {
    return fmaxf(z, 0.0f) - y * z + log1pf(expf(-fabsf(z)));
}

__device__ __forceinline__ void dot8h(__half2* acc2, const uint4& u, const __half2* th2j) {
    const __half2* h = (const __half2*)&u;
    acc2[0] = __hfma2(h[0], th2j[0], acc2[0]);
    acc2[1] = __hfma2(h[1], th2j[1], acc2[1]);
    acc2[2] = __hfma2(h[2], th2j[2], acc2[2]);
    acc2[3] = __hfma2(h[3], th2j[3], acc2[3]);
}

__device__ __forceinline__ void grad8h(__half2* gj, const uint4& u, __half2 ch2) {
    const __half2* h = (const __half2*)&u;
    gj[0] = __hfma2(ch2, h[0], gj[0]);
    gj[1] = __hfma2(ch2, h[1], gj[1]);
    gj[2] = __hfma2(ch2, h[2], gj[2]);
    gj[3] = __hfma2(ch2, h[3], gj[3]);
}

__device__ __forceinline__ float acc4_to_float(const __half2* a) {
    float2 f0 = __half22float2(a[0]);
    float2 f1 = __half22float2(a[1]);
    float2 f2 = __half22float2(a[2]);
    float2 f3 = __half22float2(a[3]);
    return (f0.x + f0.y) + (f1.x + f1.y) + (f2.x + f2.y) + (f3.x + f3.y);
}

// ---------------------------------------------------------------------------
__global__ void __launch_bounds__(NTHREADS, 1)
ak_train(const float* __restrict__ theta0,
         const float* __restrict__ yn,  const float* __restrict__ dyn,
         const float* __restrict__ alphas,
         float* __restrict__ out, int out_size) {
    extern __shared__ char smc[];
    float*  s_theta = (float*)smc;                              // DIMV fp32 (8KB)
    __half* s_grad  = (__half*)(smc + DIMV * 4);                // NWARPS*DIMV half (32KB)
    float*  s_dev   = (float*)(smc + DIMV * 4 + NWARPS * DIMV * 2);

    const int tid  = threadIdx.x;
    const int lane = tid & 31;
    const int w    = tid >> 5;
    const int cta  = blockIdx.x;
    const int ncta = gridDim.x;

    // CTA-blocked row ranges (balance <= 1 row)
    const int rb = (int)(((long long)cta * NTR) / ncta);
    const int re = (int)(((long long)(cta + 1) * NTR) / ncta);
    const int mb = (int)(((long long)cta * MDEVR) / ncta);
    const int me = (int)(((long long)(cta + 1) * MDEVR) / ncta);

    // master theta -> smem (fp32)
    for (int d = tid; d < DIMV; d += NTHREADS) s_theta[d] = theta0[d];
    __syncthreads();

    // per-thread previous integer totals for its 8 owned dims [tid*8, tid*8+8)
    long long prev[8];
#pragma unroll
    for (int i = 0; i < 8; i++) prev[i] = 0ll;
    long long devprev = 0ll;
    float isum = 0.0f;   // used by cta0/tid0 only

    __half2 th2[32];
    const __half2 hz = __float2half2_rn(0.0f);

    for (int t = 0; t < TST; ++t) {
        // ---- theta(smem fp32) -> th2 registers
        {
            const float4* t4 = (const float4*)s_theta;
#pragma unroll
            for (int j = 0; j < 8; j++) {
                float4 v0 = t4[(j*32+lane)*2 + 0];
                float4 v1 = t4[(j*32+lane)*2 + 1];
                th2[j*4+0] = __floats2half2_rn(v0.x, v0.y);
                th2[j*4+1] = __floats2half2_rn(v0.z, v0.w);
                th2[j*4+2] = __floats2half2_rn(v1.x, v1.y);
                th2[j*4+3] = __floats2half2_rn(v1.z, v1.w);
            }
        }

        // ---- train rows (CTA block, warps take consecutive pairs)
        __half2 hacc[32];
#pragma unroll
        for (int j = 0; j < 32; j++) hacc[j] = hz;

        const int rows  = re - rb;
        const int pairs = rows >> 1;
        for (int p = w; p < pairs; p += NWARPS) {
            int n0 = rb + 2*p, n1 = n0 + 1;
            const uint4* x0 = (const uint4*)(g_xn_h + (size_t)n0 * DIMV);
            const uint4* x1 = (const uint4*)(g_xn_h + (size_t)n1 * DIMV);
            __half2 a0[4] = {hz,hz,hz,hz}, a1[4] = {hz,hz,hz,hz};
#pragma unroll
            for (int j = 0; j < 8; j++) {
                uint4 ua = x0[j*32+lane];
                uint4 ub = x1[j*32+lane];
                dot8h(a0, ua, th2 + j*4);
                dot8h(a1, ub, th2 + j*4);
            }
            float z0 = warp_sum(acc4_to_float(a0));
            float z1 = warp_sum(acc4_to_float(a1));
            float s0 = 1.0f / (1.0f + expf(-z0));
            float s1 = 1.0f / (1.0f + expf(-z1));
            float c0 = alphas[(size_t)t * NTR + n0] * (s0 - yn[n0]);
            float c1 = alphas[(size_t)t * NTR + n1] * (s1 - yn[n1]);
            __half2 ch0 = __float2half2_rn(c0);
            __half2 ch1 = __float2half2_rn(c1);
#pragma unroll
            for (int j = 0; j < 8; j++) {
                uint4 ua = x0[j*32+lane];   // L1 hits
                uint4 ub = x1[j*32+lane];
                grad8h(hacc + j*4, ua, ch0);
                grad8h(hacc + j*4, ub, ch1);
            }
        }
        if ((rows & 1) && w == (pairs % NWARPS)) {   // leftover single row
            int n0 = re - 1;
            const uint4* x0 = (const uint4*)(g_xn_h + (size_t)n0 * DIMV);
            __half2 a0[4] = {hz,hz,hz,hz};
#pragma unroll
            for (int j = 0; j < 8; j++) { uint4 ua = x0[j*32+lane]; dot8h(a0, ua, th2 + j*4); }
            float z0 = warp_sum(acc4_to_float(a0));
            float s0 = 1.0f / (1.0f + expf(-z0));
            float c0 = alphas[(size_t)t * NTR + n0] * (s0 - yn[n0]);
            __half2 ch0 = __float2half2_rn(c0);
#pragma unroll
            for (int j = 0; j < 8; j++) { uint4 ua = x0[j*32+lane]; grad8h(hacc + j*4, ua, ch0); }
        }
        // per-warp grad -> smem (half2)
        {
            uint4* gp4 = (uint4*)(s_grad + (size_t)w * DIMV);
#pragma unroll
            for (int j = 0; j < 8; j++) {
                uint4 u;
                ((__half2*)&u)[0] = hacc[j*4+0];
                ((__half2*)&u)[1] = hacc[j*4+1];
                ((__half2*)&u)[2] = hacc[j*4+2];
                ((__half2*)&u)[3] = hacc[j*4+3];
                gp4[j*32+lane] = u;
            }
        }

        // ---- dev loss with theta_t (= full_losses[t])
        float dsum = 0.0f;
        {
            const int drows  = me - mb;
            const int dpairs = drows >> 1;
            for (int p = w; p < dpairs; p += NWARPS) {
                int m0 = mb + 2*p, m1 = m0 + 1;
                const uint4* x0 = (const uint4*)(g_dxn_h + (size_t)m0 * DIMV);
                const uint4* x1 = (const uint4*)(g_dxn_h + (size_t)m1 * DIMV);
                __half2 a0[4] = {hz,hz,hz,hz}, a1[4] = {hz,hz,hz,hz};
#pragma unroll
                for (int j = 0; j < 8; j++) {
                    uint4 ua = x0[j*32+lane];
                    uint4 ub = x1[j*32+lane];
                    dot8h(a0, ua, th2 + j*4);
                    dot8h(a1, ub, th2 + j*4);
                }
                float z0 = warp_sum(acc4_to_float(a0));
                float z1 = warp_sum(acc4_to_float(a1));
                dsum += dev_loss_elem(z0, dyn[m0]) + dev_loss_elem(z1, dyn[m1]);
            }
            if ((drows & 1) && w == (dpairs % NWARPS)) {
                int m0 = me - 1;
                const uint4* x0 = (const uint4*)(g_dxn_h + (size_t)m0 * DIMV);
                __half2 a0[4] = {hz,hz,hz,hz};
#pragma unroll
                for (int j = 0; j < 8; j++) { uint4 ua = x0[j*32+lane]; dot8h(a0, ua, th2 + j*4); }
                dsum += dev_loss_elem(warp_sum(acc4_to_float(a0)), dyn[m0]);
            }
        }
        if (lane == 0) s_dev[w] = dsum;
        __syncthreads();

        // ---- CTA reduce + fixed-point atomics into running totals
        if (tid == 0) {
            float s = 0.0f;
#pragma unroll
            for (int i = 0; i < NWARPS; i++) s += s_dev[i];
            atomicAdd(&g_devacc, (unsigned long long)llrintf(s * S_DEV_F));
        }
        {
            const __half2* sg2 = (const __half2*)s_grad;
#pragma unroll
            for (int i = 0; i < 4; i++) {          // (DIMV/2)/NTHREADS = 4
                int idx = tid + i * NTHREADS;      // half2 index: dims 2idx,2idx+1
                float2 s = make_float2(0.0f, 0.0f);
#pragma unroll
                for (int ww = 0; ww < NWARPS; ww++) {
                    float2 f = __half22float2(sg2[ww * (DIMV/2) + idx]);
                    s.x += f.x; s.y += f.y;
                }
                atomicAdd(&g_gradacc[2*idx+0], (unsigned long long)llrintf(s.x * S_GRAD_F));
                atomicAdd(&g_gradacc[2*idx+1], (unsigned long long)llrintf(s.y * S_GRAD_F));
            }
        }

        grid_barrier((unsigned)ncta);

        // ---- apply delta: every CTA updates its own smem theta identically
        {
            const long long* ga = (const long long*)g_gradacc;
#pragma unroll
            for (int i = 0; i < 8; i++) {
                int d = tid * 8 + i;
                long long v = ga[d];
                float g = (float)(v - prev[i]) * INV_SGRAD;
                prev[i] = v;
                s_theta[d] -= ETA * g;
            }
            if (cta == 0 && tid == 0) {
                long long dv = (long long)g_devacc;
                float Lt = (float)(dv - devprev) * INV_SDEV * (1.0f / MDEVR);
                devprev = dv;
                if (1 + t < out_size) out[1 + t] = Lt;
                if (t >= 1) isum += Lt;
            }
        }
        __syncthreads();
    }

    // ---- final dev eval at theta_T; finalize scalar loss
    {
        const float4* t4 = (const float4*)s_theta;
#pragma unroll
        for (int j = 0; j < 8; j++) {
            float4 v0 = t4[(j*32+lane)*2 + 0];
            float4 v1 = t4[(j*32+lane)*2 + 1];
            th2[j*4+0] = __floats2half2_rn(v0.x, v0.y);
            th2[j*4+1] = __floats2half2_rn(v0.z, v0.w);
            th2[j*4+2] = __floats2half2_rn(v1.x, v1.y);
            th2[j*4+3] = __floats2half2_rn(v1.z, v1.w);
        }
        float dsum = 0.0f;
        const int drows  = me - mb;
        const int dpairs = drows >> 1;
        for (int p = w; p < dpairs; p += NWARPS) {
            int m0 = mb + 2*p, m1 = m0 + 1;
            const uint4* x0 = (const uint4*)(g_dxn_h + (size_t)m0 * DIMV);
            const uint4* x1 = (const uint4*)(g_dxn_h + (size_t)m1 * DIMV);
            __half2 a0[4] = {hz,hz,hz,hz}, a1[4] = {hz,hz,hz,hz};
#pragma unroll
            for (int j = 0; j < 8; j++) {
                uint4 ua = x0[j*32+lane];
                uint4 ub = x1[j*32+lane];
                dot8h(a0, ua, th2 + j*4);
                dot8h(a1, ub, th2 + j*4);
            }
            dsum += dev_loss_elem(warp_sum(acc4_to_float(a0)), dyn[m0])
                  + dev_loss_elem(warp_sum(acc4_to_float(a1)), dyn[m1]);
        }
        if ((drows & 1) && w == (dpairs % NWARPS)) {
            int m0 = me - 1;
            const uint4* x0 = (const uint4*)(g_dxn_h + (size_t)m0 * DIMV);
            __half2 a0[4] = {hz,hz,hz,hz};
#pragma unroll
            for (int j = 0; j < 8; j++) { uint4 ua = x0[j*32+lane]; dot8h(a0, ua, th2 + j*4); }
            dsum += dev_loss_elem(warp_sum(acc4_to_float(a0)), dyn[m0]);
        }
        if (lane == 0) s_dev[w] = dsum;
        __syncthreads();
        if (tid == 0) {
            float s = 0.0f;
#pragma unroll
            for (int i = 0; i < NWARPS; i++) s += s_dev[i];
            atomicAdd(&g_devacc, (unsigned long long)llrintf(s * S_DEV_F));
        }
        grid_barrier((unsigned)ncta);
        if (cta == 0 && tid == 0) {
            long long dv = (long long)g_devacc;
            float LT = (float)(dv - devprev) * INV_SDEV * (1.0f / MDEVR);
            if (out_size > 0) out[0] = (isum + LT) / (float)TST;
        }
    }
}

// ---------------------------------------------------------------------------
extern "C" void kernel_launch(void* const* d_in, const int* in_sizes, int n_in,
                              void* d_out, int out_size) {
    const float *theta = nullptr, *alphas = nullptr, *xn = nullptr,
                *yn = nullptr, *dxn = nullptr, *dyn = nullptr;
    for (int i = 0; i < n_in; i++) {
        switch (in_sizes[i]) {
            case DIMV:         theta  = (const float*)d_in[i]; break;
            case TST * NTR:    alphas = (const float*)d_in[i]; break;
            case NTR * DIMV:   xn     = (const float*)d_in[i]; break;
            case NTR:          yn     = (const float*)d_in[i]; break;
            case MDEVR * DIMV: dxn    = (const float*)d_in[i]; break;
            case MDEVR:        dyn    = (const float*)d_in[i]; break;
            default: break;
        }
    }
    float* out = (float*)d_out;

    int dev = 0;
    cudaGetDevice(&dev);
    int nsm = 148;
    cudaDeviceGetAttribute(&nsm, cudaDevAttrMultiProcessorCount, dev);
    int ncta = nsm < 1 ? 1 : nsm;

    size_t smem = (size_t)DIMV * 4 + (size_t)NWARPS * DIMV * 2
                + NWARPS * sizeof(float);                       // ~41KB
    cudaFuncSetAttribute(ak_train, cudaFuncAttributeMaxDynamicSharedMemorySize,
                         (int)smem);

    ak_init<<<(DIMV + 255) / 256, 256>>>(out, out_size);
    ak_convert<<<4 * nsm, 256>>>(xn, dxn);
    ak_train<<<ncta, NTHREADS, smem>>>(theta, yn, dyn, alphas, out, out_size);
}